// round 12
// baseline (speedup 1.0000x reference)
#include <cuda_runtime.h>

// ---------------------------------------------------------------------------
// TemporalFootAndBall detection post-process, GB300 (sm_103a)  -- R12
//
// R12 = R10 (37.4us baseline; R11's two changes both regressed and are
// reverted) + one change: the select kernel's level-0 histogram — a ~10us
// ATOMS throughput wall (456 warp-ops x 32cyc on hot conf bins) — is moved
// into the NMS kernel, where warps idle on DRAM latency and the atomics are
// free. NMS builds a per-CTA 4096-bin smem histogram of its keepers' conf
// keys at flush time and writes it to a private global slab (no zeroing, no
// global atomics). Select sums the slabs (one batched load) and goes
// straight to threshold refinement + collect + rank.
// ---------------------------------------------------------------------------

#define B_DIM   64
#define P_H     68
#define P_W     120
#define P_HW    (P_H * P_W)
#define B_H     272
#define B_W     480
#define B_HW    (B_H * B_W)
#define MAXDET  100

#define NROWS      17                // rows per warp strip (ball & player)
#define CHUNKS_B   16                // ball row-chunks per batch (16*17=272)
#define CAP_B      (NROWS * B_W)     // 8160 (cap = pixels in chunk: safe)
#define BALL_CTAS  (B_DIM * CHUNKS_B)  // 1024
#define ALL_CTAS   (BALL_CTAS + B_DIM) // + 64 player CTAs

#define NWARP   16
#define WCAP    64                   // per-warp deferred-keeper buffer
#define NBIN    4096

// Static scratch (allocation-free).
__device__ unsigned long long g_cand_b[(size_t)BALL_CTAS * CAP_B];
__device__ unsigned long long g_cand_p[B_DIM * P_HW];
__device__ int g_cnt_b[BALL_CTAS];   // plain stores, rewritten every launch
__device__ int g_cnt_p[B_DIM];
__device__ unsigned g_hist[(size_t)ALL_CTAS * NBIN];  // per-CTA slabs

// Bit-exact replication of libdevice __nv_expf (XLA's f32 exp) for args in
// (-88, 0]. fma/exact-scale only -> fast-math-proof.
__device__ __forceinline__ float xla_expf(float a) {
    float j = fmaf(a, 0x1.715476p+0f, 0x1.8p+23f) - 0x1.8p+23f;  // rint
    float f = fmaf(j, -0x1.62e400p-1f, a);
    f = fmaf(j, -0x1.7f7d1cp-20f, f);
    const int i = (int)j;
    float r = 0x1.694000p-10f;
    r = fmaf(r, f, 0x1.125edcp-7f);
    r = fmaf(r, f, 0x1.555b5ap-5f);
    r = fmaf(r, f, 0x1.555450p-3f);
    r = fmaf(r, f, 0x1.fffff6p-2f);
    r = fmaf(r, f, 1.0f);
    r = fmaf(r, f, 1.0f);
    return r * __uint_as_float((unsigned)(127 + i) << 23);
}

// softmax([x0,x1])[1] as a function of d = x1-x0, bit-identical to
// m=max; e=exp(min-m); conf=e1/(1+e) with IEEE ops.
__device__ __forceinline__ float conf_from_d(float d) {
    const float e = xla_expf(0.0f - fabsf(d));
    const float e1 = (d >= 0.0f) ? 1.0f : e;
    return __fdiv_rn(e1, 1.0f + e);
}

// Drain a warp's deferred-keeper buffer: compute exact conf keys in bulk
// (all lanes parallel), histogram them (hidden under NMS memory latency),
// and write to the CTA's global segment.
__device__ __forceinline__ void warp_flush(unsigned long long* wb, int cnt,
                                           unsigned long long* seg,
                                           int* s_cnt, unsigned* shist,
                                           int lane) {
    if (cnt == 0) return;
    int base = 0;
    if (lane == 0) base = atomicAdd(s_cnt, cnt);
    base = __shfl_sync(0xFFFFFFFFu, base, 0);
    for (int i = lane; i < cnt; i += 32) {   // no collectives inside
        const unsigned long long e = wb[i];
        const float d = __uint_as_float((unsigned)(e >> 32));
        const unsigned key = __float_as_uint(conf_from_d(d));
        atomicAdd(&shist[key >> 20], 1u);
        seg[base + i] = ((unsigned long long)key << 32) | (unsigned)e;
    }
}

// ---------------------------------------------------------------------------
// NMS strip worker: one warp owns a 30-output-column x NROWS strip. All
// NROWS+2 halo rows of d = x1-x0 are loaded into registers up-front (single
// latency wait), then the 3x3 NMS runs register-resident.
// ---------------------------------------------------------------------------
template <int H, int W>
__device__ __forceinline__ void nms_strip(const float* __restrict__ f0,
                                          int gx, int y0,
                                          unsigned long long* wb,
                                          unsigned long long* seg,
                                          int* s_cnt, unsigned* shist,
                                          int lane) {
    const float* f1 = f0 + H * W;
    const bool inx = (gx >= 0 && gx < W);
    const bool owner = inx && lane >= 1 && lane <= 30;
    const float NINF = __int_as_float(0xFF800000);

    // Batch-load all halo rows (independent loads -> full MLP).
    float d[NROWS + 2];
    #pragma unroll
    for (int i = 0; i < NROWS + 2; ++i) {
        const int y = y0 - 1 + i;
        d[i] = NINF;
        if (inx && y >= 0 && y < H) {
            const int o = y * W + gx;
            d[i] = f1[o] - f0[o];
        }
    }

    int wcnt = 0;
    int rowbase = y0 * W;
    #pragma unroll
    for (int r = 0; r < NROWS; ++r) {
        const float vm = fmaxf(fmaxf(d[r], d[r + 1]), d[r + 2]);
        const float vl = __shfl_up_sync(0xFFFFFFFFu, vm, 1);
        const float vr = __shfl_down_sync(0xFFFFFFFFu, vm, 1);
        const float p  = fmaxf(vm, fmaxf(vl, vr));  // pooled 3x3 max (incl c)

        const float c = d[r + 1];
        bool kept = owner && (c == p);
        // Near-tie guard (per-lane, no ballot): conf bits can collapse only
        // if (p-c) <= 2^-18 * e^{dm}; exponent test, 1-bit slack each way.
        if (owner && !kept) {
            const float dd = p - c;
            const float dmx = fmaxf(fabsf(c), fabsf(p));
            const int E = (int)((__float_as_uint(dd) >> 23) & 255u) - 127;
            if ((float)E < fmaf(dmx, 1.442695041f, -15.0f)) {
                if (__float_as_uint(conf_from_d(c)) ==
                    __float_as_uint(conf_from_d(p)))
                    kept = true;
            }
        }

        const unsigned bal = __ballot_sync(0xFFFFFFFFu, kept);
        if (wcnt + 32 > WCAP) {                  // warp-uniform flush check
            warp_flush(wb, wcnt, seg, s_cnt, shist, lane);
            wcnt = 0;
        }
        if (kept)
            wb[wcnt + __popc(bal & ((1u << lane) - 1u))] =
                ((unsigned long long)__float_as_uint(c) << 32) |
                (unsigned)(rowbase + gx);
        wcnt += __popc(bal);
        rowbase += W;
    }
    warp_flush(wb, wcnt, seg, s_cnt, shist, lane);
}

// grid.x in [0, 1024): ball chunk CTAs; [1024, 1088): player CTAs.
// Block = 512 threads = 16 warps.
__global__ __launch_bounds__(512) void nms_kernel(
    const float* __restrict__ pfm, const float* __restrict__ bfm) {
    __shared__ unsigned long long wbuf[NWARP][WCAP];
    __shared__ unsigned shist[NBIN];
    __shared__ int s_cnt;
    const int tid = threadIdx.x, wid = tid >> 5, lane = tid & 31;
    if (tid == 0) s_cnt = 0;
    for (int i = tid; i < NBIN; i += 512) shist[i] = 0;
    __syncthreads();

    if (blockIdx.x < BALL_CTAS) {
        const int b = blockIdx.x >> 4, chunk = blockIdx.x & 15;
        nms_strip<B_H, B_W>(bfm + (size_t)b * 2 * B_HW,
                            wid * 30 + lane - 1, chunk * NROWS,
                            wbuf[wid],
                            g_cand_b + (size_t)blockIdx.x * CAP_B,
                            &s_cnt, shist, lane);
    } else {
        const int b = blockIdx.x - BALL_CTAS;
        const int wcol = wid & 3, rc = wid >> 2;  // 4 cols x 4 row-chunks
        nms_strip<P_H, P_W>(pfm + (size_t)b * 2 * P_HW,
                            wcol * 30 + lane - 1, rc * NROWS,
                            wbuf[wid],
                            g_cand_p + (size_t)b * P_HW,
                            &s_cnt, shist, lane);
    }
    __syncthreads();
    if (tid == 0) {
        if (blockIdx.x < BALL_CTAS) g_cnt_b[blockIdx.x] = s_cnt;
        else                        g_cnt_p[blockIdx.x - BALL_CTAS] = s_cnt;
    }
    // Write this CTA's histogram slab (disjoint -> plain stores, no zeroing).
    unsigned* slab = g_hist + (size_t)blockIdx.x * NBIN;
    for (int i = tid; i < NBIN; i += 512) slab[i] = shist[i];
}

// ---------------------------------------------------------------------------
// Block suffix scan over 1024 partials using shuffles (2 barriers).
// ---------------------------------------------------------------------------
__device__ __forceinline__ void block_suffix(unsigned part, unsigned* wsum,
                                             int wid, int lane,
                                             unsigned& sfx, unsigned& total) {
    unsigned s = part;
    #pragma unroll
    for (int d = 1; d < 32; d <<= 1) {
        const unsigned v = __shfl_down_sync(0xFFFFFFFFu, s, d);
        if (lane + d < 32) s += v;
    }
    if (lane == 0) wsum[wid] = s;
    __syncthreads();
    unsigned t = wsum[lane];           // 32 warp totals (lane-indexed)
    #pragma unroll
    for (int d = 1; d < 32; d <<= 1) {
        const unsigned v = __shfl_down_sync(0xFFFFFFFFu, t, d);
        if (lane + d < 32) t += v;
    }
    total = __shfl_sync(0xFFFFFFFFu, t, 0);
    unsigned carry = __shfl_sync(0xFFFFFFFFu, t, (wid + 1) & 31);
    if (wid == 31) carry = 0;
    sfx = s + carry;
    __syncthreads();                   // wsum reusable afterwards
}

// ---------------------------------------------------------------------------
// Per-row top-100. One CTA per output row (128 CTAs, 1024 threads).
// Level-0 histogram comes precomputed from NMS slabs (summed here with one
// batched load). Then: suffix scan -> boundary bin; rare level-1 candidate
// pass; collect; rank-emit. Candidate scans are collective-free, batch-4.
// ---------------------------------------------------------------------------
__global__ __launch_bounds__(1024) void select_kernel(
    const float* __restrict__ pbb, float* __restrict__ out) {
    constexpr int CAP = 1024;
    constexpr int NT = 1024;
    __shared__ unsigned hist[NBIN];
    __shared__ unsigned wsum[32];
    __shared__ unsigned long long buf[CAP];
    __shared__ int s_cnts[CHUNKS_B];
    __shared__ unsigned sh_b0, sh_above0, sh_set0, sh_thresh, sh_cnt, sh_done;

    const int blk = blockIdx.x;
    const bool is_player = (blk < B_DIM);
    const int b = is_player ? blk : blk - B_DIM;
    const int tid = threadIdx.x, wid = tid >> 5, lane = tid & 31;
    const int nseg = is_player ? 1 : CHUNKS_B;
    const int myseg = wid & (nseg - 1);        // warp's segment
    const int sub = wid / nseg;                // warp index within segment
    const int sstride = (32 / nseg) * 32;      // lanes per segment per iter

    if (tid < nseg)
        s_cnts[tid] = is_player ? g_cnt_p[b] : g_cnt_b[b * CHUNKS_B + tid];
    if (tid == 0) { sh_cnt = 0; sh_done = 0; sh_thresh = 0; }
    __syncthreads();

    const unsigned long long* const segp =
        is_player ? (g_cand_p + (size_t)b * P_HW)
                  : (g_cand_b + (size_t)(b * CHUNKS_B + myseg) * CAP_B);
    const int mycnt = s_cnts[myseg];           // warp-uniform
    const int mynit = (mycnt + sstride - 1) / sstride;
    const int lbase = sub * 32 + lane;

    // ---- Level 0: sum precomputed NMS slabs (independent loads, 1 wait) ----
    const int slab0 = is_player ? (BALL_CTAS + b) : (b * CHUNKS_B);
    unsigned h0 = 0, h1 = 0, h2 = 0, h3 = 0;
    for (int s = 0; s < nseg; ++s) {
        const unsigned* hp = g_hist + (size_t)(slab0 + s) * NBIN + 4 * tid;
        h0 += hp[0]; h1 += hp[1]; h2 += hp[2]; h3 += hp[3];
    }

    {
        const unsigned part = h0 + h1 + h2 + h3;
        unsigned sfx, total;
        block_suffix(part, wsum, wid, lane, sfx, total);
        const unsigned sfxn = sfx - part;
        if (total < (unsigned)MAXDET) {
            if (tid == 0) sh_done = 1;         // collect-all path
        } else if (sfx >= (unsigned)MAXDET && sfxn < (unsigned)MAXDET) {
            unsigned acc = sfxn;
            const unsigned hh[4] = {h0, h1, h2, h3};
            for (int k = 3; k >= 0; --k) {
                if (acc + hh[k] >= (unsigned)MAXDET) {
                    sh_b0 = (unsigned)(4 * tid + k);
                    sh_above0 = acc;
                    sh_set0 = acc + hh[k];
                    break;
                }
                acc += hh[k];
            }
        }
    }
    __syncthreads();

    unsigned thresh = 0;
    if (!sh_done) {
        if (sh_set0 <= 140u) {
            thresh = sh_b0 << 20;
        } else {
            // ---- Level 1 within boundary bin (bins = bits 19:8) ----
            // Bins genuinely spread here: plain atomics, batch-4 loads.
            const unsigned b0 = sh_b0;
            const unsigned target = (unsigned)MAXDET - sh_above0;
            for (int i = tid; i < NBIN; i += NT) hist[i] = 0;
            __syncthreads();
            for (int it = 0; it < mynit; it += 4) {
                unsigned sc[4];
                bool on[4];
                #pragma unroll
                for (int k = 0; k < 4; ++k) {
                    const int i = (it + k) * sstride + lbase;
                    const bool v = (i < mycnt);
                    sc[k] = v ? (unsigned)(segp[i] >> 32) : 0u;
                    on[k] = v && ((sc[k] >> 20) == b0);
                }
                #pragma unroll
                for (int k = 0; k < 4; ++k)
                    if (on[k]) atomicAdd(&hist[(sc[k] >> 8) & 0xFFFu], 1u);
            }
            __syncthreads();
            const unsigned g0 = hist[4 * tid],     g1 = hist[4 * tid + 1];
            const unsigned g2 = hist[4 * tid + 2], g3 = hist[4 * tid + 3];
            const unsigned part = g0 + g1 + g2 + g3;
            unsigned sfx, total;
            block_suffix(part, wsum, wid, lane, sfx, total);
            const unsigned sfxn = sfx - part;
            if (sfx >= target && sfxn < target) {  // total >= target holds
                unsigned acc = sfxn;
                const unsigned hh[4] = {g0, g1, g2, g3};
                for (int k = 3; k >= 0; --k) {
                    if (acc + hh[k] >= target) {
                        sh_thresh = (b0 << 20) |
                                    ((unsigned)(4 * tid + k) << 8);
                        break;
                    }
                    acc += hh[k];
                }
            }
            __syncthreads();
            thresh = sh_thresh;
        }
    }

    // ---- Collect candidates >= thresh (collective-free; keepers rare) ----
    // key = (conf_bits<<32) | ~idx : larger == (higher conf, lower idx)
    // == lax.top_k order.
    for (int it = 0; it < mynit; it += 4) {
        unsigned long long cv[4];
        bool keep[4];
        #pragma unroll
        for (int k = 0; k < 4; ++k) {
            const int i = (it + k) * sstride + lbase;
            const bool v = (i < mycnt);
            cv[k] = v ? segp[i] : 0ull;
            keep[k] = v && ((unsigned)(cv[k] >> 32) >= thresh);
        }
        #pragma unroll
        for (int k = 0; k < 4; ++k)
            if (keep[k]) {
                const unsigned pos = atomicAdd(&sh_cnt, 1u);
                if (pos < (unsigned)CAP)
                    buf[pos] = (cv[k] & 0xFFFFFFFF00000000ull) |
                               (unsigned)(~(unsigned)cv[k]);
            }
    }
    __syncthreads();
    const int m = (int)min(sh_cnt, (unsigned)CAP);

    // ---- Rank-based emission (keys distinct -> ranks a permutation) ----
    float* const orow = out + (size_t)b * (2 * MAXDET * 5) +
                        (is_player ? 0 : MAXDET * 5);
    for (int i = tid; i < m; i += NT) {
        const unsigned long long k = buf[i];
        int rank = 0;
        for (int j = 0; j < m; ++j) rank += (buf[j] > k);
        if (rank < MAXDET) {
            const unsigned idx = ~(unsigned)k;
            const float conf = __uint_as_float((unsigned)(k >> 32));
            float o0, o1, o2, o3;
            if (is_player) {
                const int x = (int)idx % P_W;
                const int y = (int)idx / P_W;
                const float xc = (float)x * 16.0f + 7.5f;
                const float yc = (float)y * 16.0f + 7.5f;
                const float* bp = pbb + (size_t)b * 4 * P_HW + idx;
                const float t0 = bp[0 * P_HW] * 1920.0f;
                const float t1 = bp[1 * P_HW] * 1088.0f;
                const float t2 = bp[2 * P_HW] * 1920.0f;
                const float t3 = bp[3 * P_HW] * 1088.0f;
                const float bx = xc + t0, by = yc + t1;
                o0 = bx - 0.5f * t2;
                o1 = by - 0.5f * t3;
                o2 = bx + 0.5f * t2;
                o3 = by + 0.5f * t3;
            } else {
                const int x = (int)idx % B_W;
                const int y = (int)idx / B_W;
                const float xc = (float)x * 4.0f + 1.5f;
                const float yc = (float)y * 4.0f + 1.5f;
                o0 = xc - 10.0f;
                o1 = yc - 10.0f;
                o2 = xc + 10.0f;
                o3 = yc + 10.0f;
            }
            float* op = orow + rank * 5;
            op[0] = o0; op[1] = o1; op[2] = o2; op[3] = o3; op[4] = conf;
        }
    }
    if (m < MAXDET) {  // pathological; never hit with this data
        for (int r = m + tid; r < MAXDET; r += NT) {
            float* op = orow + r * 5;
            op[0] = op[1] = op[2] = op[3] = op[4] = 0.0f;
        }
    }
}

// ---------------------------------------------------------------------------

extern "C" void kernel_launch(void* const* d_in, const int* in_sizes, int n_in,
                              void* d_out, int out_size) {
    const float* pfm = nullptr;
    const float* pbb = nullptr;
    const float* bfm = nullptr;
    for (int i = 0; i < n_in; ++i) {
        if (in_sizes[i] == B_DIM * 2 * P_HW)      pfm = (const float*)d_in[i];
        else if (in_sizes[i] == B_DIM * 4 * P_HW) pbb = (const float*)d_in[i];
        else if (in_sizes[i] == B_DIM * 2 * B_HW) bfm = (const float*)d_in[i];
    }
    float* out = (float*)d_out;

    nms_kernel<<<ALL_CTAS, 512>>>(pfm, bfm);
    select_kernel<<<2 * B_DIM, 1024>>>(pbb, out);
}

// round 13
// speedup vs baseline: 1.2549x; 1.2549x over previous
#include <cuda_runtime.h>

// ---------------------------------------------------------------------------
// TemporalFootAndBall detection post-process, GB300 (sm_103a)  -- R13
//
// R13 = R10 (best: 37.4us; R11/R12 experiments both regressed and are fully
// reverted) + ONE change in select: range-adaptive level-0 binning.
// conf>=0.5 (exponent 126, where nearly all candidates cluster) bins on
// MANTISSA bits -> 2048 uniform 2^12-ulp bins (~7 cand/bin) instead of 8 hot
// bins. Below 0.5 bins by exponent. Boundary set drops to ~110: the level-1
// refinement pass is skipped in the common case (3 passes -> 2) and the
// O(m^2) rank loop shrinks ~4x. Level-1 kept as generic sub-bin fallback.
// ---------------------------------------------------------------------------

#define B_DIM   64
#define P_H     68
#define P_W     120
#define P_HW    (P_H * P_W)
#define B_H     272
#define B_W     480
#define B_HW    (B_H * B_W)
#define MAXDET  100

#define NROWS      17                // rows per warp strip (ball & player)
#define CHUNKS_B   16                // ball row-chunks per batch (16*17=272)
#define CAP_B      (NROWS * B_W)     // 8160 (cap = pixels in chunk: safe)
#define BALL_CTAS  (B_DIM * CHUNKS_B)  // 1024
#define ALL_CTAS   (BALL_CTAS + B_DIM) // + 64 player CTAs

#define NWARP   16
#define WCAP    64                   // per-warp deferred-keeper buffer

// Static scratch (allocation-free).
__device__ unsigned long long g_cand_b[(size_t)BALL_CTAS * CAP_B];
__device__ unsigned long long g_cand_p[B_DIM * P_HW];
__device__ int g_cnt_b[BALL_CTAS];   // plain stores, rewritten every launch
__device__ int g_cnt_p[B_DIM];

// Bit-exact replication of libdevice __nv_expf (XLA's f32 exp) for args in
// (-88, 0]. fma/exact-scale only -> fast-math-proof.
__device__ __forceinline__ float xla_expf(float a) {
    float j = fmaf(a, 0x1.715476p+0f, 0x1.8p+23f) - 0x1.8p+23f;  // rint
    float f = fmaf(j, -0x1.62e400p-1f, a);
    f = fmaf(j, -0x1.7f7d1cp-20f, f);
    const int i = (int)j;
    float r = 0x1.694000p-10f;
    r = fmaf(r, f, 0x1.125edcp-7f);
    r = fmaf(r, f, 0x1.555b5ap-5f);
    r = fmaf(r, f, 0x1.555450p-3f);
    r = fmaf(r, f, 0x1.fffff6p-2f);
    r = fmaf(r, f, 1.0f);
    r = fmaf(r, f, 1.0f);
    return r * __uint_as_float((unsigned)(127 + i) << 23);
}

// softmax([x0,x1])[1] as a function of d = x1-x0, bit-identical to
// m=max; e=exp(min-m); conf=e1/(1+e) with IEEE ops.
__device__ __forceinline__ float conf_from_d(float d) {
    const float e = xla_expf(0.0f - fabsf(d));
    const float e1 = (d >= 0.0f) ? 1.0f : e;
    return __fdiv_rn(e1, 1.0f + e);
}

// Range-adaptive monotone bin map for conf keys (conf in (0,1]):
//   key >= 0x3F000000 (conf >= 0.5): mantissa bins, 2^12 ulps wide
//   else: exponent bins (coarse; sparse population)
__device__ __forceinline__ unsigned key_bin(unsigned key) {
    return (key >= 0x3F000000u) ? (128u + ((key - 0x3F000000u) >> 12))
                                : (key >> 23);
}
__device__ __forceinline__ unsigned bin_lo(unsigned b) {
    return (b >= 128u) ? (0x3F000000u + ((b - 128u) << 12)) : (b << 23);
}
__device__ __forceinline__ int bin_shift(unsigned b) {
    return (b >= 128u) ? 0 : 11;   // sub-bin width shift for level-1
}

// Drain a warp's deferred-keeper buffer: compute exact conf keys in bulk
// (all lanes parallel) and write to the CTA's global segment.
__device__ __forceinline__ void warp_flush(unsigned long long* wb, int cnt,
                                           unsigned long long* seg,
                                           int* s_cnt, int lane) {
    if (cnt == 0) return;
    int base = 0;
    if (lane == 0) base = atomicAdd(s_cnt, cnt);
    base = __shfl_sync(0xFFFFFFFFu, base, 0);
    for (int i = lane; i < cnt; i += 32) {   // no collectives inside
        const unsigned long long e = wb[i];
        const float d = __uint_as_float((unsigned)(e >> 32));
        const unsigned key = __float_as_uint(conf_from_d(d));
        seg[base + i] = ((unsigned long long)key << 32) | (unsigned)e;
    }
}

// ---------------------------------------------------------------------------
// NMS strip worker: one warp owns a 30-output-column x NROWS strip. All
// NROWS+2 halo rows of d = x1-x0 are loaded into registers up-front (single
// latency wait), then the 3x3 NMS runs register-resident.
// ---------------------------------------------------------------------------
template <int H, int W>
__device__ __forceinline__ void nms_strip(const float* __restrict__ f0,
                                          int gx, int y0,
                                          unsigned long long* wb,
                                          unsigned long long* seg,
                                          int* s_cnt, int lane) {
    const float* f1 = f0 + H * W;
    const bool inx = (gx >= 0 && gx < W);
    const bool owner = inx && lane >= 1 && lane <= 30;
    const float NINF = __int_as_float(0xFF800000);

    // Batch-load all halo rows (independent loads -> full MLP).
    float d[NROWS + 2];
    #pragma unroll
    for (int i = 0; i < NROWS + 2; ++i) {
        const int y = y0 - 1 + i;
        d[i] = NINF;
        if (inx && y >= 0 && y < H) {
            const int o = y * W + gx;
            d[i] = f1[o] - f0[o];
        }
    }

    int wcnt = 0;
    int rowbase = y0 * W;
    #pragma unroll
    for (int r = 0; r < NROWS; ++r) {
        const float vm = fmaxf(fmaxf(d[r], d[r + 1]), d[r + 2]);
        const float vl = __shfl_up_sync(0xFFFFFFFFu, vm, 1);
        const float vr = __shfl_down_sync(0xFFFFFFFFu, vm, 1);
        const float p  = fmaxf(vm, fmaxf(vl, vr));  // pooled 3x3 max (incl c)

        const float c = d[r + 1];
        bool kept = owner && (c == p);
        // Near-tie guard (per-lane, no ballot): conf bits can collapse only
        // if (p-c) <= 2^-18 * e^{dm}; exponent test, 1-bit slack each way.
        if (owner && !kept) {
            const float dd = p - c;
            const float dmx = fmaxf(fabsf(c), fabsf(p));
            const int E = (int)((__float_as_uint(dd) >> 23) & 255u) - 127;
            if ((float)E < fmaf(dmx, 1.442695041f, -15.0f)) {
                if (__float_as_uint(conf_from_d(c)) ==
                    __float_as_uint(conf_from_d(p)))
                    kept = true;
            }
        }

        const unsigned bal = __ballot_sync(0xFFFFFFFFu, kept);
        if (wcnt + 32 > WCAP) {                  // warp-uniform flush check
            warp_flush(wb, wcnt, seg, s_cnt, lane);
            wcnt = 0;
        }
        if (kept)
            wb[wcnt + __popc(bal & ((1u << lane) - 1u))] =
                ((unsigned long long)__float_as_uint(c) << 32) |
                (unsigned)(rowbase + gx);
        wcnt += __popc(bal);
        rowbase += W;
    }
    warp_flush(wb, wcnt, seg, s_cnt, lane);
}

// grid.x in [0, 1024): ball chunk CTAs; [1024, 1088): player CTAs.
// Block = 512 threads = 16 warps.
__global__ __launch_bounds__(512) void nms_kernel(
    const float* __restrict__ pfm, const float* __restrict__ bfm) {
    __shared__ unsigned long long wbuf[NWARP][WCAP];
    __shared__ int s_cnt;
    const int tid = threadIdx.x, wid = tid >> 5, lane = tid & 31;
    if (tid == 0) s_cnt = 0;
    __syncthreads();

    if (blockIdx.x < BALL_CTAS) {
        const int b = blockIdx.x >> 4, chunk = blockIdx.x & 15;
        nms_strip<B_H, B_W>(bfm + (size_t)b * 2 * B_HW,
                            wid * 30 + lane - 1, chunk * NROWS,
                            wbuf[wid],
                            g_cand_b + (size_t)blockIdx.x * CAP_B,
                            &s_cnt, lane);
    } else {
        const int b = blockIdx.x - BALL_CTAS;
        const int wcol = wid & 3, rc = wid >> 2;  // 4 cols x 4 row-chunks
        nms_strip<P_H, P_W>(pfm + (size_t)b * 2 * P_HW,
                            wcol * 30 + lane - 1, rc * NROWS,
                            wbuf[wid],
                            g_cand_p + (size_t)b * P_HW,
                            &s_cnt, lane);
    }
    __syncthreads();
    if (tid == 0) {
        if (blockIdx.x < BALL_CTAS) g_cnt_b[blockIdx.x] = s_cnt;
        else                        g_cnt_p[blockIdx.x - BALL_CTAS] = s_cnt;
    }
}

// ---------------------------------------------------------------------------
// Block suffix scan over 1024 partials using shuffles (2 barriers).
// ---------------------------------------------------------------------------
__device__ __forceinline__ void block_suffix(unsigned part, unsigned* wsum,
                                             int wid, int lane,
                                             unsigned& sfx, unsigned& total) {
    unsigned s = part;
    #pragma unroll
    for (int d = 1; d < 32; d <<= 1) {
        const unsigned v = __shfl_down_sync(0xFFFFFFFFu, s, d);
        if (lane + d < 32) s += v;
    }
    if (lane == 0) wsum[wid] = s;
    __syncthreads();
    unsigned t = wsum[lane];           // 32 warp totals (lane-indexed)
    #pragma unroll
    for (int d = 1; d < 32; d <<= 1) {
        const unsigned v = __shfl_down_sync(0xFFFFFFFFu, t, d);
        if (lane + d < 32) t += v;
    }
    total = __shfl_sync(0xFFFFFFFFu, t, 0);
    unsigned carry = __shfl_sync(0xFFFFFFFFu, t, (wid + 1) & 31);
    if (wid == 31) carry = 0;
    sfx = s + carry;
    __syncthreads();                   // wsum reusable afterwards
}

// ---------------------------------------------------------------------------
// Per-row top-100. One CTA per output row (128 CTAs, 1024 threads).
// Warps spread across 16 segments (2 warps each); scan loops collective-free
// with batch-4 loads. Range-adaptive binning -> boundary set ~110 ->
// level-1 usually skipped and rank loop short.
// ---------------------------------------------------------------------------
__global__ __launch_bounds__(1024) void select_kernel(
    const float* __restrict__ pbb, float* __restrict__ out) {
    constexpr int CAP = 1024;
    constexpr int NT = 1024;
    __shared__ unsigned hist[4096];
    __shared__ unsigned wsum[32];
    __shared__ unsigned long long buf[CAP];
    __shared__ int s_cnts[CHUNKS_B];
    __shared__ unsigned sh_b0, sh_above0, sh_set0, sh_thresh, sh_cnt, sh_done;

    const int blk = blockIdx.x;
    const bool is_player = (blk < B_DIM);
    const int b = is_player ? blk : blk - B_DIM;
    const int tid = threadIdx.x, wid = tid >> 5, lane = tid & 31;
    const int nseg = is_player ? 1 : CHUNKS_B;
    const int myseg = wid & (nseg - 1);        // warp's segment
    const int sub = wid / nseg;                // warp index within segment
    const int sstride = (32 / nseg) * 32;      // lanes per segment per iter

    if (tid < nseg)
        s_cnts[tid] = is_player ? g_cnt_p[b] : g_cnt_b[b * CHUNKS_B + tid];
    if (tid == 0) { sh_cnt = 0; sh_done = 0; sh_thresh = 0; }
    for (int i = tid; i < 4096; i += NT) hist[i] = 0;
    __syncthreads();

    const unsigned long long* const segp =
        is_player ? (g_cand_p + (size_t)b * P_HW)
                  : (g_cand_b + (size_t)(b * CHUNKS_B + myseg) * CAP_B);
    const int mycnt = s_cnts[myseg];           // warp-uniform
    const int mynit = (mycnt + sstride - 1) / sstride;
    const int lbase = sub * 32 + lane;

    // ---- Level 0 histogram (range-adaptive bins) ----
    // Batch-4 independent loads, plain smem atomics (bins well-spread now).
    for (int it = 0; it < mynit; it += 4) {
        unsigned bins[4];
        bool on[4];
        #pragma unroll
        for (int k = 0; k < 4; ++k) {
            const int i = (it + k) * sstride + lbase;
            on[k] = (i < mycnt);
            bins[k] = on[k] ? key_bin((unsigned)(segp[i] >> 32)) : 0u;
        }
        #pragma unroll
        for (int k = 0; k < 4; ++k)
            if (on[k]) atomicAdd(&hist[bins[k]], 1u);
    }
    __syncthreads();

    {
        const unsigned h0 = hist[4 * tid],     h1 = hist[4 * tid + 1];
        const unsigned h2 = hist[4 * tid + 2], h3 = hist[4 * tid + 3];
        const unsigned part = h0 + h1 + h2 + h3;
        unsigned sfx, total;
        block_suffix(part, wsum, wid, lane, sfx, total);
        const unsigned sfxn = sfx - part;
        if (total < (unsigned)MAXDET) {
            if (tid == 0) sh_done = 1;         // collect-all path
        } else if (sfx >= (unsigned)MAXDET && sfxn < (unsigned)MAXDET) {
            unsigned acc = sfxn;
            const unsigned hh[4] = {h0, h1, h2, h3};
            for (int k = 3; k >= 0; --k) {
                if (acc + hh[k] >= (unsigned)MAXDET) {
                    sh_b0 = (unsigned)(4 * tid + k);
                    sh_above0 = acc;
                    sh_set0 = acc + hh[k];
                    break;
                }
                acc += hh[k];
            }
        }
    }
    __syncthreads();

    unsigned thresh = 0;
    if (!sh_done) {
        if (sh_set0 <= 168u) {                 // common: fine bins -> small set
            thresh = bin_lo(sh_b0);
        } else {
            // ---- Level 1 within boundary bin (generic sub-bins) ----
            const unsigned b0 = sh_b0;
            const unsigned lo = bin_lo(b0);
            const int sh = bin_shift(b0);      // 0 (exact) or 11
            const unsigned target = (unsigned)MAXDET - sh_above0;
            for (int i = tid; i < 4096; i += NT) hist[i] = 0;
            __syncthreads();
            for (int it = 0; it < mynit; it += 4) {
                unsigned sc[4];
                bool on[4];
                #pragma unroll
                for (int k = 0; k < 4; ++k) {
                    const int i = (it + k) * sstride + lbase;
                    const bool v = (i < mycnt);
                    sc[k] = v ? (unsigned)(segp[i] >> 32) : 0u;
                    on[k] = v && (key_bin(sc[k]) == b0);
                }
                #pragma unroll
                for (int k = 0; k < 4; ++k)
                    if (on[k])
                        atomicAdd(&hist[((sc[k] - lo) >> sh) & 0xFFFu], 1u);
            }
            __syncthreads();
            const unsigned g0 = hist[4 * tid],     g1 = hist[4 * tid + 1];
            const unsigned g2 = hist[4 * tid + 2], g3 = hist[4 * tid + 3];
            const unsigned part = g0 + g1 + g2 + g3;
            unsigned sfx, total;
            block_suffix(part, wsum, wid, lane, sfx, total);
            const unsigned sfxn = sfx - part;
            if (sfx >= target && sfxn < target) {  // total >= target holds
                unsigned acc = sfxn;
                const unsigned hh[4] = {g0, g1, g2, g3};
                for (int k = 3; k >= 0; --k) {
                    if (acc + hh[k] >= target) {
                        sh_thresh = lo + ((unsigned)(4 * tid + k) << sh);
                        break;
                    }
                    acc += hh[k];
                }
            }
            __syncthreads();
            thresh = sh_thresh;
        }
    }

    // ---- Collect candidates >= thresh (collective-free; keepers rare) ----
    // key = (conf_bits<<32) | ~idx : larger == (higher conf, lower idx)
    // == lax.top_k order.
    for (int it = 0; it < mynit; it += 4) {
        unsigned long long cv[4];
        bool keep[4];
        #pragma unroll
        for (int k = 0; k < 4; ++k) {
            const int i = (it + k) * sstride + lbase;
            const bool v = (i < mycnt);
            cv[k] = v ? segp[i] : 0ull;
            keep[k] = v && ((unsigned)(cv[k] >> 32) >= thresh);
        }
        #pragma unroll
        for (int k = 0; k < 4; ++k)
            if (keep[k]) {
                const unsigned pos = atomicAdd(&sh_cnt, 1u);
                if (pos < (unsigned)CAP)
                    buf[pos] = (cv[k] & 0xFFFFFFFF00000000ull) |
                               (unsigned)(~(unsigned)cv[k]);
            }
    }
    __syncthreads();
    const int m = (int)min(sh_cnt, (unsigned)CAP);

    // ---- Rank-based emission (keys distinct -> ranks a permutation) ----
    float* const orow = out + (size_t)b * (2 * MAXDET * 5) +
                        (is_player ? 0 : MAXDET * 5);
    for (int i = tid; i < m; i += NT) {
        const unsigned long long k = buf[i];
        int rank = 0;
        for (int j = 0; j < m; ++j) rank += (buf[j] > k);
        if (rank < MAXDET) {
            const unsigned idx = ~(unsigned)k;
            const float conf = __uint_as_float((unsigned)(k >> 32));
            float o0, o1, o2, o3;
            if (is_player) {
                const int x = (int)idx % P_W;
                const int y = (int)idx / P_W;
                const float xc = (float)x * 16.0f + 7.5f;
                const float yc = (float)y * 16.0f + 7.5f;
                const float* bp = pbb + (size_t)b * 4 * P_HW + idx;
                const float t0 = bp[0 * P_HW] * 1920.0f;
                const float t1 = bp[1 * P_HW] * 1088.0f;
                const float t2 = bp[2 * P_HW] * 1920.0f;
                const float t3 = bp[3 * P_HW] * 1088.0f;
                const float bx = xc + t0, by = yc + t1;
                o0 = bx - 0.5f * t2;
                o1 = by - 0.5f * t3;
                o2 = bx + 0.5f * t2;
                o3 = by + 0.5f * t3;
            } else {
                const int x = (int)idx % B_W;
                const int y = (int)idx / B_W;
                const float xc = (float)x * 4.0f + 1.5f;
                const float yc = (float)y * 4.0f + 1.5f;
                o0 = xc - 10.0f;
                o1 = yc - 10.0f;
                o2 = xc + 10.0f;
                o3 = yc + 10.0f;
            }
            float* op = orow + rank * 5;
            op[0] = o0; op[1] = o1; op[2] = o2; op[3] = o3; op[4] = conf;
        }
    }
    if (m < MAXDET) {  // pathological; never hit with this data
        for (int r = m + tid; r < MAXDET; r += NT) {
            float* op = orow + r * 5;
            op[0] = op[1] = op[2] = op[3] = op[4] = 0.0f;
        }
    }
}

// ---------------------------------------------------------------------------

extern "C" void kernel_launch(void* const* d_in, const int* in_sizes, int n_in,
                              void* d_out, int out_size) {
    const float* pfm = nullptr;
    const float* pbb = nullptr;
    const float* bfm = nullptr;
    for (int i = 0; i < n_in; ++i) {
        if (in_sizes[i] == B_DIM * 2 * P_HW)      pfm = (const float*)d_in[i];
        else if (in_sizes[i] == B_DIM * 4 * P_HW) pbb = (const float*)d_in[i];
        else if (in_sizes[i] == B_DIM * 2 * B_HW) bfm = (const float*)d_in[i];
    }
    float* out = (float*)d_out;

    nms_kernel<<<ALL_CTAS, 512>>>(pfm, bfm);
    select_kernel<<<2 * B_DIM, 1024>>>(pbb, out);
}